// round 5
// baseline (speedup 1.0000x reference)
#include <cuda_runtime.h>
#include <cuda_bf16.h>
#include <math.h>

#define NRES 768
#define HN   12
#define CH   16
#define CZ   128
#define PQN  4
#define PVN  8
#define CS   384

// ---------------- scratch (device globals; no allocation) ----------------
__device__ float g_q   [NRES * HN * CH];          // [n][h*16+c]
__device__ float g_kv  [NRES * HN * 2 * CH];      // [n][h*32+c] (k: c<16, v: c>=16)
__device__ float g_qp  [NRES * HN * PQN * 3];     // raw qp proj  [n][144]
__device__ float g_kvp [NRES * HN * 12 * 3];      // raw kvp proj [n][432]
__device__ float g_qpts[NRES * HN * PQN * 3];     // [n][h*12 + p*3 + i]
__device__ float g_kpts[NRES * HN * PQN * 3];     // [n][h*12 + p*3 + i]
__device__ float g_vpts[NRES * HN * PVN * 3];     // [n][h*24 + p*3 + i]
__device__ float g_a   [HN * NRES * NRES];        // [h][n][m]
__device__ float g_obuf[NRES * HN * 40];          // [n][h][c] c<16: o ; 16..39: o_pt global
__device__ float g_ocat[NRES * 2112];             // concat features per n

// ---------------- GEMM body: C = A (768 x K) * W^T (Nc x K) + bias ---------
__device__ __forceinline__ void gemm_body(const float* __restrict__ A,
                                          const float* __restrict__ W,
                                          const float* __restrict__ bias,
                                          float* __restrict__ C,
                                          int Nc, int K, int bm, int bn,
                                          float (*As)[68], float (*Bs)[68]) {
    const int tid = threadIdx.x;
    const int ty = tid >> 4, tx = tid & 15;
    float acc[4][4];
#pragma unroll
    for (int i = 0; i < 4; i++)
#pragma unroll
        for (int j = 0; j < 4; j++) acc[i][j] = 0.f;

    for (int k0 = 0; k0 < K; k0 += 32) {
#pragma unroll
        for (int i = 0; i < 8; i++) {
            int idx = tid + i * 256;
            int r = idx >> 5, c = idx & 31;
            As[c][r] = A[(size_t)(bm + r) * K + k0 + c];
            int j = bn + r;
            Bs[c][r] = (j < Nc) ? W[(size_t)j * K + k0 + c] : 0.f;
        }
        __syncthreads();
#pragma unroll
        for (int kk = 0; kk < 32; kk++) {
            float ra[4], rb[4];
#pragma unroll
            for (int i = 0; i < 4; i++) ra[i] = As[kk][ty * 4 + i];
#pragma unroll
            for (int j = 0; j < 4; j++) rb[j] = Bs[kk][tx * 4 + j];
#pragma unroll
            for (int i = 0; i < 4; i++)
#pragma unroll
                for (int j = 0; j < 4; j++) acc[i][j] += ra[i] * rb[j];
        }
        __syncthreads();
    }
#pragma unroll
    for (int i = 0; i < 4; i++) {
        int m = bm + ty * 4 + i;
#pragma unroll
        for (int j = 0; j < 4; j++) {
            int jj = bn + tx * 4 + j;
            if (jj < Nc) C[(size_t)m * Nc + jj] = acc[i][j] + bias[jj];
        }
    }
}

__global__ void gemm_abt(const float* __restrict__ A, const float* __restrict__ W,
                         const float* __restrict__ bias, float* __restrict__ C,
                         int Nc, int K) {
    __shared__ float As[32][68];
    __shared__ float Bs[32][68];
    gemm_body(A, W, bias, C, Nc, K, blockIdx.y * 64, blockIdx.x * 64, As, Bs);
}

// ---------------- all 4 projections in one launch ---------------------------
// column tiles: q 3 | kv 6 | qp 3 | kvp 7  => blockIdx.x in [0,19)
__global__ void gemm_proj(const float* __restrict__ s,
                          const float* __restrict__ w_q,  const float* __restrict__ b_q,  float* pq,
                          const float* __restrict__ w_kv, const float* __restrict__ b_kv, float* pkv,
                          const float* __restrict__ w_qp, const float* __restrict__ b_qp, float* pqp,
                          const float* __restrict__ w_kvp,const float* __restrict__ b_kvp,float* pkvp) {
    __shared__ float As[32][68];
    __shared__ float Bs[32][68];
    const int x = blockIdx.x;
    const float *W, *bias; float* C; int Nc, bn;
    if (x < 3)       { W = w_q;   bias = b_q;   C = pq;   Nc = 192; bn = x; }
    else if (x < 9)  { W = w_kv;  bias = b_kv;  C = pkv;  Nc = 384; bn = x - 3; }
    else if (x < 12) { W = w_qp;  bias = b_qp;  C = pqp;  Nc = 144; bn = x - 9; }
    else             { W = w_kvp; bias = b_kvp; C = pkvp; Nc = 432; bn = x - 12; }
    gemm_body(s, W, bias, C, Nc, CS, blockIdx.y * 64, bn * 64, As, Bs);
}

// ---------------- point transform: rotate+translate projected points -------
__global__ void k_points(const float* __restrict__ rot, const float* __restrict__ trans) {
    int n = blockIdx.x;
    int t = threadIdx.x;   // 192 threads
    const float* r = rot + n * 9;
    float t0 = trans[n * 3 + 0], t1 = trans[n * 3 + 1], t2 = trans[n * 3 + 2];
    if (t < 48) {
        float x = g_qp[n * 144 + t];
        float y = g_qp[n * 144 + 48 + t];
        float z = g_qp[n * 144 + 96 + t];
        float o0 = r[0] * x + r[1] * y + r[2] * z + t0;
        float o1 = r[3] * x + r[4] * y + r[5] * z + t1;
        float o2 = r[6] * x + r[7] * y + r[8] * z + t2;
        g_qpts[n * 144 + t * 3 + 0] = o0;
        g_qpts[n * 144 + t * 3 + 1] = o1;
        g_qpts[n * 144 + t * 3 + 2] = o2;
    } else {
        int p = t - 48;  // 0..143 = h*12 + pp
        float x = g_kvp[n * 432 + p];
        float y = g_kvp[n * 432 + 144 + p];
        float z = g_kvp[n * 432 + 288 + p];
        float o0 = r[0] * x + r[1] * y + r[2] * z + t0;
        float o1 = r[3] * x + r[4] * y + r[5] * z + t1;
        float o2 = r[6] * x + r[7] * y + r[8] * z + t2;
        int h = p / 12, pp = p % 12;
        if (pp < 4) {
            int base = n * 144 + (h * 4 + pp) * 3;
            g_kpts[base + 0] = o0; g_kpts[base + 1] = o1; g_kpts[base + 2] = o2;
        } else {
            int base = n * 288 + (h * 8 + (pp - 4)) * 3;
            g_vpts[base + 0] = o0; g_vpts[base + 1] = o1; g_vpts[base + 2] = o2;
        }
    }
}

// ---------------- bmat: a[h][n][m] = sqrt(1/3)*(z[n,m]·w_b[h] + b_b[h]) ----
// grid (mt=6, n=768), 128 threads. Register tile 4m x 3h (7 LDS / 12 FMA).
// zsh pad 129: thread m's strided by 32 -> conflict-free; w reads broadcast.
#define BM_MT 128
#define BM_ZPAD 129
__global__ void k_bmat(const float* __restrict__ z, const float* __restrict__ w_b,
                       const float* __restrict__ b_b) {
    extern __shared__ float sh[];
    float* zsh = sh;                       // [128][129]
    float* wsh = sh + BM_MT * BM_ZPAD;     // [12][128]
    const int n = blockIdx.y;
    const int m0 = blockIdx.x * BM_MT;
    const int tid = threadIdx.x;

    const float* zp = z + ((size_t)n * NRES + m0) * CZ;
    for (int idx = tid; idx < BM_MT * CZ; idx += 128) {
        int m = idx >> 7, c = idx & 127;
        zsh[m * BM_ZPAD + c] = zp[idx];
    }
    for (int idx = tid; idx < HN * CZ; idx += 128) wsh[idx] = w_b[idx];
    __syncthreads();

    const int mg = tid & 31;       // m lane
    const int hg = tid >> 5;       // h group (0..3), 3 heads each
    float acc[4][3];
#pragma unroll
    for (int i = 0; i < 4; i++)
#pragma unroll
        for (int j = 0; j < 3; j++) acc[i][j] = 0.f;

#pragma unroll 4
    for (int c = 0; c < CZ; c++) {
        float zv[4], wv[3];
#pragma unroll
        for (int i = 0; i < 4; i++) zv[i] = zsh[(mg + 32 * i) * BM_ZPAD + c];
#pragma unroll
        for (int j = 0; j < 3; j++) wv[j] = wsh[(hg * 3 + j) * CZ + c];
#pragma unroll
        for (int i = 0; i < 4; i++)
#pragma unroll
            for (int j = 0; j < 3; j++) acc[i][j] += zv[i] * wv[j];
    }
#pragma unroll
    for (int j = 0; j < 3; j++) {
        int h = hg * 3 + j;
        float bb = b_b[h];
#pragma unroll
        for (int i = 0; i < 4; i++) {
            g_a[((size_t)h * NRES + n) * NRES + m0 + mg + 32 * i] =
                0.5773502691896258f * (acc[i][j] + bb);
        }
    }
}

// ---------------- logits add: qk + point-attn + mask (in place on g_a) -----
__global__ void k_logits(const float* __restrict__ mask,
                         const float* __restrict__ head_weights) {
    __shared__ float ksh[256 * 17];    // k[m][16] pad 17
    __shared__ float kpsh[256 * 13];   // k_pts[m][12] pad 13
    __shared__ float msh[256];
    const int h = blockIdx.x;
    const int n0 = blockIdx.y * 32;
    const int tid = threadIdx.x;
    const int row = tid >> 4;
    const int mcol = tid & 15;

    const int nA = n0 + row * 2, nB = nA + 1;
    float qA[16], qB[16], pA[12], pB[12];
#pragma unroll
    for (int c = 0; c < 16; c++) {
        qA[c] = g_q[nA * 192 + h * 16 + c];
        qB[c] = g_q[nB * 192 + h * 16 + c];
    }
#pragma unroll
    for (int c = 0; c < 12; c++) {
        pA[c] = g_qpts[nA * 144 + h * 12 + c];
        pB[c] = g_qpts[nB * 144 + h * 12 + c];
    }
    const float maskA = mask[nA], maskB = mask[nB];
    const float s1 = 0.14433756729740643f;                 // sqrt(1/48)
    const float hw = log1pf(expf(head_weights[h]));
    const float wpt = -0.5f * hw * 0.13608276348795434f;   // sqrt(1/54)

    for (int mt = 0; mt < 3; mt++) {
        const int mbase = mt * 256;
        __syncthreads();
        for (int idx = tid; idx < 256 * 16; idx += 256) {
            int m = idx >> 4, c = idx & 15;
            ksh[m * 17 + c] = g_kv[(size_t)(mbase + m) * 384 + h * 32 + c];
        }
        for (int idx = tid; idx < 256 * 12; idx += 256) {
            int m = idx / 12, c = idx % 12;
            kpsh[m * 13 + c] = g_kpts[(mbase + m) * 144 + h * 12 + c];
        }
        if (tid < 256) msh[tid] = mask[mbase + tid];
        __syncthreads();
#pragma unroll 1
        for (int kk = 0; kk < 16; kk++) {
            int ml = mcol + kk * 16;
            const float* kr = &ksh[ml * 17];
            const float* kp = &kpsh[ml * 13];
            float qkA = 0.f, qkB = 0.f;
#pragma unroll
            for (int c = 0; c < 16; c++) { float kv = kr[c]; qkA += qA[c] * kv; qkB += qB[c] * kv; }
            float ptA = 0.f, ptB = 0.f;
#pragma unroll
            for (int c = 0; c < 12; c++) {
                float kv = kp[c];
                float dA = pA[c] - kv; ptA += dA * dA;
                float dB = pB[c] - kv; ptB += dB * dB;
            }
            float mm = msh[ml];
            float addA = qkA * s1 + wpt * ptA + (maskA * mm - 1.f) * 100000.f;
            float addB = qkB * s1 + wpt * ptB + (maskB * mm - 1.f) * 100000.f;
            size_t iA = ((size_t)h * NRES + nA) * NRES + mbase + ml;
            size_t iB = ((size_t)h * NRES + nB) * NRES + mbase + ml;
            g_a[iA] += addA;
            g_a[iB] += addB;
        }
    }
}

// ---------------- softmax over m (row = h*768 + n) --------------------------
__global__ void k_softmax() {
    __shared__ float red[256];
    const size_t row = blockIdx.x;
    float* a = g_a + row * NRES;
    const int t = threadIdx.x;
    float v0 = a[t], v1 = a[t + 256], v2 = a[t + 512];
    float mx = fmaxf(v0, fmaxf(v1, v2));
    red[t] = mx; __syncthreads();
    for (int s = 128; s > 0; s >>= 1) {
        if (t < s) red[t] = fmaxf(red[t], red[t + s]);
        __syncthreads();
    }
    mx = red[0];
    __syncthreads();
    v0 = expf(v0 - mx); v1 = expf(v1 - mx); v2 = expf(v2 - mx);
    red[t] = v0 + v1 + v2; __syncthreads();
    for (int s = 128; s > 0; s >>= 1) {
        if (t < s) red[t] += red[t + s];
        __syncthreads();
    }
    float inv = 1.f / red[0];
    a[t] = v0 * inv; a[t + 256] = v1 * inv; a[t + 512] = v2 * inv;
}

// ---------------- o = a@v, o_pt = a@v_pts (global frame) --------------------
__global__ void k_av() {
    __shared__ float ash[64 * 65];
    __shared__ float vsh[64 * 48];   // 40 data cols, padded (speculative reads stay in-bounds)
    const int h = blockIdx.x;
    const int n0 = blockIdx.y * 64;
    const int tid = threadIdx.x;
    const int nq = tid & 15, cg = tid >> 4;   // 16 x 16
    float acc[4][3];
#pragma unroll
    for (int i = 0; i < 4; i++)
#pragma unroll
        for (int j = 0; j < 3; j++) acc[i][j] = 0.f;

    for (int mt = 0; mt < 12; mt++) {
        const int m0 = mt * 64;
        __syncthreads();
        for (int idx = tid; idx < 4096; idx += 256) {
            int nn = idx >> 6, mm = idx & 63;
            ash[nn * 65 + mm] = g_a[((size_t)h * NRES + n0 + nn) * NRES + m0 + mm];
        }
        for (int idx = tid; idx < 64 * 48; idx += 256) {
            int mm = idx / 48, c = idx % 48;
            float v = 0.f;
            if (c < 16)      v = g_kv[(size_t)(m0 + mm) * 384 + h * 32 + 16 + c];
            else if (c < 40) v = g_vpts[(m0 + mm) * 288 + h * 24 + (c - 16)];
            vsh[mm * 48 + c] = v;
        }
        __syncthreads();
#pragma unroll 4
        for (int mm = 0; mm < 64; mm++) {
            float ra[4], rv[3];
#pragma unroll
            for (int i = 0; i < 4; i++) ra[i] = ash[(nq + 16 * i) * 65 + mm];
#pragma unroll
            for (int j = 0; j < 3; j++) rv[j] = vsh[mm * 48 + cg + 16 * j];
#pragma unroll
            for (int i = 0; i < 4; i++)
#pragma unroll
                for (int j = 0; j < 3; j++) acc[i][j] += ra[i] * rv[j];
        }
    }
#pragma unroll
    for (int i = 0; i < 4; i++) {
        int n = n0 + nq + 16 * i;
#pragma unroll
        for (int j = 0; j < 3; j++) {
            int c = cg + 16 * j;
            if (c < 40) g_obuf[((size_t)n * 12 + h) * 40 + c] = acc[i][j];
        }
    }
}

// ---------------- o_pair = a @ z (second z pass) -----------------------------
// grid 768 (n), 128 threads. Thread tile 3h x 4c (7 LDS / 12 FMA).
#define OP_MT 64
#define OP_ZPAD 129
__global__ void k_opair(const float* __restrict__ z) {
    extern __shared__ float sh[];
    float* ash = sh;                         // [12][768]
    float* zsh = sh + HN * NRES;             // [64][129]
    const int n = blockIdx.x;
    const int tid = threadIdx.x;

    for (int idx = tid; idx < HN * NRES; idx += 128) {
        int h = idx / NRES, m = idx % NRES;
        ash[idx] = g_a[((size_t)h * NRES + n) * NRES + m];
    }

    const int cg = tid & 31;    // c lane (c = cg + 32*i)
    const int hg = tid >> 5;    // h group (3 heads each)
    float acc[3][4];
#pragma unroll
    for (int j = 0; j < 3; j++)
#pragma unroll
        for (int i = 0; i < 4; i++) acc[j][i] = 0.f;

    for (int mt = 0; mt < NRES / OP_MT; mt++) {
        __syncthreads();
        const float* zp = z + ((size_t)n * NRES + mt * OP_MT) * CZ;
        for (int idx = tid; idx < OP_MT * CZ; idx += 128) {
            int m = idx >> 7, c = idx & 127;
            zsh[m * OP_ZPAD + c] = zp[idx];
        }
        __syncthreads();
#pragma unroll 4
        for (int mm = 0; mm < OP_MT; mm++) {
            float zv[4], av[3];
#pragma unroll
            for (int i = 0; i < 4; i++) zv[i] = zsh[mm * OP_ZPAD + cg + 32 * i];
#pragma unroll
            for (int j = 0; j < 3; j++) av[j] = ash[(hg * 3 + j) * NRES + mt * OP_MT + mm];
#pragma unroll
            for (int j = 0; j < 3; j++)
#pragma unroll
                for (int i = 0; i < 4; i++) acc[j][i] += av[j] * zv[i];
        }
    }
#pragma unroll
    for (int j = 0; j < 3; j++) {
        int h = hg * 3 + j;
#pragma unroll
        for (int i = 0; i < 4; i++) {
            g_ocat[(size_t)n * 2112 + 576 + h * 128 + cg + 32 * i] = acc[j][i];
        }
    }
}

// ---------------- finalize: o_pt to local frame, norms, concat --------------
__global__ void k_finish(const float* __restrict__ rot, const float* __restrict__ trans) {
    const int n = blockIdx.x;
    const int t = threadIdx.x;   // 192
    if (t < 96) {
        int h = t >> 3, p = t & 7;
        const float* ob = &g_obuf[((size_t)n * 12 + h) * 40 + 16 + p * 3];
        float gx = ob[0] - trans[n * 3 + 0];
        float gy = ob[1] - trans[n * 3 + 1];
        float gz = ob[2] - trans[n * 3 + 2];
        const float* r = rot + n * 9;
        float lx = r[0] * gx + r[3] * gy + r[6] * gz;
        float ly = r[1] * gx + r[4] * gy + r[7] * gz;
        float lz = r[2] * gx + r[5] * gy + r[8] * gz;
        size_t base = (size_t)n * 2112;
        g_ocat[base + 192 + t] = lx;
        g_ocat[base + 288 + t] = ly;
        g_ocat[base + 384 + t] = lz;
        g_ocat[base + 480 + t] = sqrtf(lx * lx + ly * ly + lz * lz + 1e-8f);
    }
    g_ocat[(size_t)n * 2112 + t] = g_obuf[((size_t)n * 12 + (t >> 4)) * 40 + (t & 15)];
}

// ---------------- launcher ---------------------------------------------------
extern "C" void kernel_launch(void* const* d_in, const int* in_sizes, int n_in,
                              void* d_out, int out_size) {
    const float* s      = (const float*)d_in[0];
    const float* z      = (const float*)d_in[1];
    const float* rot    = (const float*)d_in[2];
    const float* trans  = (const float*)d_in[3];
    const float* mask   = (const float*)d_in[4];
    const float* w_q    = (const float*)d_in[5];
    const float* b_q    = (const float*)d_in[6];
    const float* w_kv   = (const float*)d_in[7];
    const float* b_kv   = (const float*)d_in[8];
    const float* w_qp   = (const float*)d_in[9];
    const float* b_qp   = (const float*)d_in[10];
    const float* w_kvp  = (const float*)d_in[11];
    const float* b_kvp  = (const float*)d_in[12];
    const float* w_b    = (const float*)d_in[13];
    const float* b_b    = (const float*)d_in[14];
    const float* hwts   = (const float*)d_in[15];
    const float* w_out  = (const float*)d_in[16];
    const float* b_out  = (const float*)d_in[17];
    float* out = (float*)d_out;

    float *pq, *pkv, *pqp, *pkvp, *pocat;
    cudaGetSymbolAddress((void**)&pq,    g_q);
    cudaGetSymbolAddress((void**)&pkv,   g_kv);
    cudaGetSymbolAddress((void**)&pqp,   g_qp);
    cudaGetSymbolAddress((void**)&pkvp,  g_kvp);
    cudaGetSymbolAddress((void**)&pocat, g_ocat);

    const int bmat_smem  = (BM_MT * BM_ZPAD + HN * CZ) * 4;        // ~72.2 KB
    const int opair_smem = (HN * NRES + OP_MT * OP_ZPAD) * 4;      // ~69.9 KB
    cudaFuncSetAttribute(k_bmat,  cudaFuncAttributeMaxDynamicSharedMemorySize, bmat_smem);
    cudaFuncSetAttribute(k_opair, cudaFuncAttributeMaxDynamicSharedMemorySize, opair_smem);

    // projections (one launch)
    gemm_proj<<<dim3(19, 12), 256>>>(s, w_q, b_q, pq, w_kv, b_kv, pkv,
                                     w_qp, b_qp, pqp, w_kvp, b_kvp, pkvp);
    // point transform
    k_points<<<NRES, 192>>>(rot, trans);
    // logits: bmat (z pass 1), then qk + pt + mask
    k_bmat<<<dim3(NRES / BM_MT, NRES), 128, bmat_smem>>>(z, w_b, b_b);
    k_logits<<<dim3(12, 24), 256>>>(mask, hwts);
    // softmax
    k_softmax<<<HN * NRES, 256>>>();
    // attention outputs
    k_av<<<dim3(12, 12), 256>>>();
    k_opair<<<NRES, 128, opair_smem>>>(z);   // z pass 2
    k_finish<<<NRES, 192>>>(rot, trans);
    // output projection
    gemm_abt<<<dim3(6, 12), 256>>>(pocat, w_out, b_out, out, 384, 2112);
}

// round 6
// speedup vs baseline: 1.4044x; 1.4044x over previous
#include <cuda_runtime.h>
#include <cuda_bf16.h>
#include <math.h>

#define NRES 768
#define HN   12
#define CH   16
#define CZ   128
#define PQN  4
#define PVN  8
#define CS   384

// ---------------- scratch (device globals; no allocation) ----------------
__device__ float g_q   [NRES * HN * CH];          // [n][h*16+c]
__device__ float g_kv  [NRES * HN * 2 * CH];      // [n][h*32+c] (k: c<16, v: c>=16)
__device__ float g_qp  [NRES * HN * PQN * 3];     // raw qp proj  [n][144]
__device__ float g_kvp [NRES * HN * 12 * 3];      // raw kvp proj [n][432]
__device__ float g_qpts[NRES * HN * PQN * 3];     // [n][h*12 + p*3 + i]
__device__ float g_kpts[NRES * HN * PQN * 3];     // [n][h*12 + p*3 + i]
__device__ float g_vpts[NRES * HN * PVN * 3];     // [n][h*24 + p*3 + i]
__device__ float g_a   [HN * NRES * NRES];        // [h][n][m]
__device__ float g_obuf[NRES * HN * 40];          // [n][h][c] c<16: o ; 16..39: o_pt global
__device__ float g_ocat[NRES * 2112];             // concat features per n

// ---------------- GEMM body: C = A (768 x K) * W^T (Nc x K) + bias ---------
__device__ __forceinline__ void gemm_body(const float* __restrict__ A,
                                          const float* __restrict__ W,
                                          const float* __restrict__ bias,
                                          float* __restrict__ C,
                                          int Nc, int K, int bm, int bn,
                                          float (*As)[68], float (*Bs)[68]) {
    const int tid = threadIdx.x;
    const int ty = tid >> 4, tx = tid & 15;
    float acc[4][4];
#pragma unroll
    for (int i = 0; i < 4; i++)
#pragma unroll
        for (int j = 0; j < 4; j++) acc[i][j] = 0.f;

    for (int k0 = 0; k0 < K; k0 += 32) {
#pragma unroll
        for (int i = 0; i < 8; i++) {
            int idx = tid + i * 256;
            int r = idx >> 5, c = idx & 31;
            As[c][r] = A[(size_t)(bm + r) * K + k0 + c];
            int j = bn + r;
            Bs[c][r] = (j < Nc) ? W[(size_t)j * K + k0 + c] : 0.f;
        }
        __syncthreads();
#pragma unroll
        for (int kk = 0; kk < 32; kk++) {
            float ra[4], rb[4];
#pragma unroll
            for (int i = 0; i < 4; i++) ra[i] = As[kk][ty * 4 + i];
#pragma unroll
            for (int j = 0; j < 4; j++) rb[j] = Bs[kk][tx * 4 + j];
#pragma unroll
            for (int i = 0; i < 4; i++)
#pragma unroll
                for (int j = 0; j < 4; j++) acc[i][j] += ra[i] * rb[j];
        }
        __syncthreads();
    }
#pragma unroll
    for (int i = 0; i < 4; i++) {
        int m = bm + ty * 4 + i;
#pragma unroll
        for (int j = 0; j < 4; j++) {
            int jj = bn + tx * 4 + j;
            if (jj < Nc) C[(size_t)m * Nc + jj] = acc[i][j] + bias[jj];
        }
    }
}

__global__ void gemm_abt(const float* __restrict__ A, const float* __restrict__ W,
                         const float* __restrict__ bias, float* __restrict__ C,
                         int Nc, int K) {
    __shared__ float As[32][68];
    __shared__ float Bs[32][68];
    gemm_body(A, W, bias, C, Nc, K, blockIdx.y * 64, blockIdx.x * 64, As, Bs);
}

// ---------------- all 4 projections in one launch ---------------------------
__global__ void gemm_proj(const float* __restrict__ s,
                          const float* __restrict__ w_q,  const float* __restrict__ b_q,  float* pq,
                          const float* __restrict__ w_kv, const float* __restrict__ b_kv, float* pkv,
                          const float* __restrict__ w_qp, const float* __restrict__ b_qp, float* pqp,
                          const float* __restrict__ w_kvp,const float* __restrict__ b_kvp,float* pkvp) {
    __shared__ float As[32][68];
    __shared__ float Bs[32][68];
    const int x = blockIdx.x;
    const float *W, *bias; float* C; int Nc, bn;
    if (x < 3)       { W = w_q;   bias = b_q;   C = pq;   Nc = 192; bn = x; }
    else if (x < 9)  { W = w_kv;  bias = b_kv;  C = pkv;  Nc = 384; bn = x - 3; }
    else if (x < 12) { W = w_qp;  bias = b_qp;  C = pqp;  Nc = 144; bn = x - 9; }
    else             { W = w_kvp; bias = b_kvp; C = pkvp; Nc = 432; bn = x - 12; }
    gemm_body(s, W, bias, C, Nc, CS, blockIdx.y * 64, bn * 64, As, Bs);
}

// ---------------- point transform: rotate+translate projected points -------
__global__ void k_points(const float* __restrict__ rot, const float* __restrict__ trans) {
    int n = blockIdx.x;
    int t = threadIdx.x;   // 192 threads
    const float* r = rot + n * 9;
    float t0 = trans[n * 3 + 0], t1 = trans[n * 3 + 1], t2 = trans[n * 3 + 2];
    if (t < 48) {
        float x = g_qp[n * 144 + t];
        float y = g_qp[n * 144 + 48 + t];
        float z = g_qp[n * 144 + 96 + t];
        float o0 = r[0] * x + r[1] * y + r[2] * z + t0;
        float o1 = r[3] * x + r[4] * y + r[5] * z + t1;
        float o2 = r[6] * x + r[7] * y + r[8] * z + t2;
        g_qpts[n * 144 + t * 3 + 0] = o0;
        g_qpts[n * 144 + t * 3 + 1] = o1;
        g_qpts[n * 144 + t * 3 + 2] = o2;
    } else {
        int p = t - 48;  // 0..143 = h*12 + pp
        float x = g_kvp[n * 432 + p];
        float y = g_kvp[n * 432 + 144 + p];
        float z = g_kvp[n * 432 + 288 + p];
        float o0 = r[0] * x + r[1] * y + r[2] * z + t0;
        float o1 = r[3] * x + r[4] * y + r[5] * z + t1;
        float o2 = r[6] * x + r[7] * y + r[8] * z + t2;
        int h = p / 12, pp = p % 12;
        if (pp < 4) {
            int base = n * 144 + (h * 4 + pp) * 3;
            g_kpts[base + 0] = o0; g_kpts[base + 1] = o1; g_kpts[base + 2] = o2;
        } else {
            int base = n * 288 + (h * 8 + (pp - 4)) * 3;
            g_vpts[base + 0] = o0; g_vpts[base + 1] = o1; g_vpts[base + 2] = o2;
        }
    }
}

// ---------------- qk + point-attn + mask -> E in g_a ------------------------
// grid (m-tile 12, n-tile 12, h 12), 256 threads. K=28: c<16 qk (q pre-scaled
// by s1), c in [16,28) point dims (both sides pre-scaled by sqrt(|wpt|), acc -= d^2).
__global__ void k_qkpt(const float* __restrict__ mask,
                       const float* __restrict__ head_weights) {
    __shared__ float Qs[28][68];
    __shared__ float Ks[28][68];
    const int h  = blockIdx.z;
    const int n0 = blockIdx.y * 64;
    const int m0 = blockIdx.x * 64;
    const int tid = threadIdx.x;
    const float s1 = 0.14433756729740643f;                    // sqrt(1/48)
    const float hw = log1pf(expf(head_weights[h]));
    const float wpt_abs = 0.5f * hw * 0.13608276348795434f;   // 0.5*hw*sqrt(1/54)
    const float sp = sqrtf(wpt_abs);

    for (int idx = tid; idx < 64 * 32; idx += 256) {
        int c = idx & 31, r = idx >> 5;
        if (c < 16) {
            Qs[c][r] = s1 * g_q[(n0 + r) * 192 + h * 16 + c];
            Ks[c][r] = g_kv[(size_t)(m0 + r) * 384 + h * 32 + c];
        } else if (c < 28) {
            Qs[c][r] = sp * g_qpts[(n0 + r) * 144 + h * 12 + (c - 16)];
            Ks[c][r] = sp * g_kpts[(m0 + r) * 144 + h * 12 + (c - 16)];
        }
    }
    __syncthreads();
    const int ty = tid >> 4, tx = tid & 15;
    float acc[4][4];
#pragma unroll
    for (int i = 0; i < 4; i++)
#pragma unroll
        for (int j = 0; j < 4; j++) acc[i][j] = 0.f;

#pragma unroll
    for (int c = 0; c < 16; c++) {
        float ra[4], rb[4];
#pragma unroll
        for (int i = 0; i < 4; i++) ra[i] = Qs[c][ty * 4 + i];
#pragma unroll
        for (int j = 0; j < 4; j++) rb[j] = Ks[c][tx * 4 + j];
#pragma unroll
        for (int i = 0; i < 4; i++)
#pragma unroll
            for (int j = 0; j < 4; j++) acc[i][j] += ra[i] * rb[j];
    }
#pragma unroll
    for (int c = 16; c < 28; c++) {
        float ra[4], rb[4];
#pragma unroll
        for (int i = 0; i < 4; i++) ra[i] = Qs[c][ty * 4 + i];
#pragma unroll
        for (int j = 0; j < 4; j++) rb[j] = Ks[c][tx * 4 + j];
#pragma unroll
        for (int i = 0; i < 4; i++)
#pragma unroll
            for (int j = 0; j < 4; j++) {
                float d = ra[i] - rb[j];
                acc[i][j] = fmaf(-d, d, acc[i][j]);
            }
    }
#pragma unroll
    for (int i = 0; i < 4; i++) {
        int n = n0 + ty * 4 + i;
        float mn = mask[n];
#pragma unroll
        for (int j = 0; j < 4; j++) {
            int m = m0 + tx * 4 + j;
            g_a[((size_t)h * NRES + n) * NRES + m] =
                acc[i][j] + (mn * mask[m] - 1.f) * 100000.f;
        }
    }
}

// ---------------- fused scores: E + sqrt(1/3)*(z.w_b + b_b), softmax --------
// one block per n, 256 threads. L[12][768] resident in smem; z row streamed
// in 64-m tiles (float4, pad 132). Writes final softmaxed a to g_a once.
#define SC_LSZ   (HN * NRES)             // 9216
#define SC_ZPAD  132
#define SC_ZSZ   (64 * SC_ZPAD)          // 8448
#define SC_SMEM  ((SC_LSZ + SC_ZSZ + HN * CZ + 16) * 4)
__global__ void k_scores(const float* __restrict__ z, const float* __restrict__ w_b,
                         const float* __restrict__ b_b) {
    extern __shared__ float sh[];
    float* Lsh = sh;                       // 9216
    float* zsh = Lsh + SC_LSZ;             // 8448
    float* wsh = zsh + SC_ZSZ;             // 1536
    float* bsh = wsh + HN * CZ;            // 12
    const int n = blockIdx.x;
    const int tid = threadIdx.x;

    for (int idx = tid; idx < SC_LSZ; idx += 256) {
        int h = idx / NRES, m = idx - h * NRES;
        Lsh[idx] = g_a[((size_t)h * NRES + n) * NRES + m];
    }
    for (int idx = tid; idx < HN * CZ; idx += 256) wsh[idx] = w_b[idx];
    if (tid < HN) bsh[tid] = b_b[tid];

    const int hg = tid >> 6;      // 0..3, 3 heads each
    const int mg = tid & 63;
    const float s3 = 0.5773502691896258f;

    for (int mt = 0; mt < 12; mt++) {
        const int m0 = mt * 64;
        __syncthreads();
        const float4* zp = (const float4*)(z + ((size_t)n * NRES + m0) * CZ);
        for (int idx = tid; idx < 64 * 32; idx += 256) {
            int m = idx >> 5, c4 = idx & 31;
            float4 v = zp[m * 32 + c4];
            *(float4*)&zsh[m * SC_ZPAD + c4 * 4] = v;
        }
        __syncthreads();
        float a0 = 0.f, a1 = 0.f, a2 = 0.f;
        const float* zr = &zsh[mg * SC_ZPAD];
        const float* w0 = &wsh[(hg * 3 + 0) * CZ];
        const float* w1 = &wsh[(hg * 3 + 1) * CZ];
        const float* w2 = &wsh[(hg * 3 + 2) * CZ];
#pragma unroll 8
        for (int c4 = 0; c4 < 32; c4++) {
            float4 zv = *(const float4*)&zr[c4 * 4];
            float4 v0 = *(const float4*)&w0[c4 * 4];
            float4 v1 = *(const float4*)&w1[c4 * 4];
            float4 v2 = *(const float4*)&w2[c4 * 4];
            a0 += zv.x * v0.x + zv.y * v0.y + zv.z * v0.z + zv.w * v0.w;
            a1 += zv.x * v1.x + zv.y * v1.y + zv.z * v1.z + zv.w * v1.w;
            a2 += zv.x * v2.x + zv.y * v2.y + zv.z * v2.z + zv.w * v2.w;
        }
        Lsh[(hg * 3 + 0) * NRES + m0 + mg] += s3 * (a0 + bsh[hg * 3 + 0]);
        Lsh[(hg * 3 + 1) * NRES + m0 + mg] += s3 * (a1 + bsh[hg * 3 + 1]);
        Lsh[(hg * 3 + 2) * NRES + m0 + mg] += s3 * (a2 + bsh[hg * 3 + 2]);
    }
    __syncthreads();

    // softmax per head row (warp per row, wrap for h >= 8)
    const int wid = tid >> 5, lane = tid & 31;
    for (int h = wid; h < HN; h += 8) {
        float* row = &Lsh[h * NRES];
        float mx = -1e30f;
        for (int i = lane; i < NRES; i += 32) mx = fmaxf(mx, row[i]);
#pragma unroll
        for (int o = 16; o > 0; o >>= 1) mx = fmaxf(mx, __shfl_xor_sync(0xffffffffu, mx, o));
        float sum = 0.f;
        for (int i = lane; i < NRES; i += 32) {
            float e = expf(row[i] - mx);
            row[i] = e;
            sum += e;
        }
#pragma unroll
        for (int o = 16; o > 0; o >>= 1) sum += __shfl_xor_sync(0xffffffffu, sum, o);
        float inv = 1.f / sum;
        float* out = &g_a[((size_t)h * NRES + n) * NRES];
        for (int i = lane; i < NRES; i += 32) out[i] = row[i] * inv;
    }
}

// ---------------- o = a@v, o_pt = a@v_pts (global frame) --------------------
__global__ void k_av() {
    __shared__ float ash[64 * 65];
    __shared__ float vsh[64 * 48];
    const int h = blockIdx.x;
    const int n0 = blockIdx.y * 64;
    const int tid = threadIdx.x;
    const int nq = tid & 15, cg = tid >> 4;
    float acc[4][3];
#pragma unroll
    for (int i = 0; i < 4; i++)
#pragma unroll
        for (int j = 0; j < 3; j++) acc[i][j] = 0.f;

    for (int mt = 0; mt < 12; mt++) {
        const int m0 = mt * 64;
        __syncthreads();
        for (int idx = tid; idx < 4096; idx += 256) {
            int nn = idx >> 6, mm = idx & 63;
            ash[nn * 65 + mm] = g_a[((size_t)h * NRES + n0 + nn) * NRES + m0 + mm];
        }
        for (int idx = tid; idx < 64 * 48; idx += 256) {
            int mm = idx / 48, c = idx % 48;
            float v = 0.f;
            if (c < 16)      v = g_kv[(size_t)(m0 + mm) * 384 + h * 32 + 16 + c];
            else if (c < 40) v = g_vpts[(m0 + mm) * 288 + h * 24 + (c - 16)];
            vsh[mm * 48 + c] = v;
        }
        __syncthreads();
#pragma unroll 4
        for (int mm = 0; mm < 64; mm++) {
            float ra[4], rv[3];
#pragma unroll
            for (int i = 0; i < 4; i++) ra[i] = ash[(nq + 16 * i) * 65 + mm];
#pragma unroll
            for (int j = 0; j < 3; j++) rv[j] = vsh[mm * 48 + cg + 16 * j];
#pragma unroll
            for (int i = 0; i < 4; i++)
#pragma unroll
                for (int j = 0; j < 3; j++) acc[i][j] += ra[i] * rv[j];
        }
    }
#pragma unroll
    for (int i = 0; i < 4; i++) {
        int n = n0 + nq + 16 * i;
#pragma unroll
        for (int j = 0; j < 3; j++) {
            int c = cg + 16 * j;
            if (c < 40) g_obuf[((size_t)n * 12 + h) * 40 + c] = acc[i][j];
        }
    }
}

// ---------------- o_pair = a @ z (second z pass), float4 version ------------
// one block per n, 256 threads = 8 m-partitions x 32 c-groups (4c each).
// per m: 1 LDG.128 (z) + 12 broadcast LDS (a) + 48 FMA. smem reduce over 8.
#define OP_ASZ  (HN * NRES)          // 9216
#define OP_PSZ  (8 * HN * CZ)        // 12288
#define OP_SMEM ((OP_ASZ + OP_PSZ) * 4)
__global__ void k_opair(const float* __restrict__ z) {
    extern __shared__ float sh[];
    float* ash  = sh;                 // [12][768]
    float* psum = sh + OP_ASZ;        // [8][12][128]
    const int n = blockIdx.x;
    const int tid = threadIdx.x;

    for (int idx = tid; idx < OP_ASZ; idx += 256) {
        int h = idx / NRES, m = idx - h * NRES;
        ash[idx] = g_a[((size_t)h * NRES + n) * NRES + m];
    }
    __syncthreads();

    const int mp = tid >> 5;   // 0..7
    const int cg = tid & 31;   // 0..31 (4 c's)
    float acc[12][4];
#pragma unroll
    for (int h = 0; h < 12; h++)
#pragma unroll
        for (int k = 0; k < 4; k++) acc[h][k] = 0.f;

    const float4* zb = (const float4*)(z + (size_t)n * NRES * CZ);
    const int mstart = mp * 96;
#pragma unroll 2
    for (int mm = 0; mm < 96; mm++) {
        int m = mstart + mm;
        float4 zv = zb[(size_t)m * 32 + cg];
        float av[12];
#pragma unroll
        for (int h = 0; h < 12; h++) av[h] = ash[h * NRES + m];
#pragma unroll
        for (int h = 0; h < 12; h++) {
            acc[h][0] += av[h] * zv.x;
            acc[h][1] += av[h] * zv.y;
            acc[h][2] += av[h] * zv.z;
            acc[h][3] += av[h] * zv.w;
        }
    }
#pragma unroll
    for (int h = 0; h < 12; h++) {
        *(float4*)&psum[(mp * 12 + h) * CZ + cg * 4] =
            make_float4(acc[h][0], acc[h][1], acc[h][2], acc[h][3]);
    }
    __syncthreads();
    for (int out = tid; out < HN * CZ; out += 256) {
        int h = out >> 7, c = out & 127;
        float s = 0.f;
#pragma unroll
        for (int p = 0; p < 8; p++) s += psum[(p * 12 + h) * CZ + c];
        g_ocat[(size_t)n * 2112 + 576 + h * CZ + c] = s;
    }
}

// ---------------- finalize: o_pt to local frame, norms, concat --------------
__global__ void k_finish(const float* __restrict__ rot, const float* __restrict__ trans) {
    const int n = blockIdx.x;
    const int t = threadIdx.x;   // 192
    if (t < 96) {
        int h = t >> 3, p = t & 7;
        const float* ob = &g_obuf[((size_t)n * 12 + h) * 40 + 16 + p * 3];
        float gx = ob[0] - trans[n * 3 + 0];
        float gy = ob[1] - trans[n * 3 + 1];
        float gz = ob[2] - trans[n * 3 + 2];
        const float* r = rot + n * 9;
        float lx = r[0] * gx + r[3] * gy + r[6] * gz;
        float ly = r[1] * gx + r[4] * gy + r[7] * gz;
        float lz = r[2] * gx + r[5] * gy + r[8] * gz;
        size_t base = (size_t)n * 2112;
        g_ocat[base + 192 + t] = lx;
        g_ocat[base + 288 + t] = ly;
        g_ocat[base + 384 + t] = lz;
        g_ocat[base + 480 + t] = sqrtf(lx * lx + ly * ly + lz * lz + 1e-8f);
    }
    g_ocat[(size_t)n * 2112 + t] = g_obuf[((size_t)n * 12 + (t >> 4)) * 40 + (t & 15)];
}

// ---------------- launcher ---------------------------------------------------
extern "C" void kernel_launch(void* const* d_in, const int* in_sizes, int n_in,
                              void* d_out, int out_size) {
    const float* s      = (const float*)d_in[0];
    const float* z      = (const float*)d_in[1];
    const float* rot    = (const float*)d_in[2];
    const float* trans  = (const float*)d_in[3];
    const float* mask   = (const float*)d_in[4];
    const float* w_q    = (const float*)d_in[5];
    const float* b_q    = (const float*)d_in[6];
    const float* w_kv   = (const float*)d_in[7];
    const float* b_kv   = (const float*)d_in[8];
    const float* w_qp   = (const float*)d_in[9];
    const float* b_qp   = (const float*)d_in[10];
    const float* w_kvp  = (const float*)d_in[11];
    const float* b_kvp  = (const float*)d_in[12];
    const float* w_b    = (const float*)d_in[13];
    const float* b_b    = (const float*)d_in[14];
    const float* hwts   = (const float*)d_in[15];
    const float* w_out  = (const float*)d_in[16];
    const float* b_out  = (const float*)d_in[17];
    float* out = (float*)d_out;

    float *pq, *pkv, *pqp, *pkvp, *pocat;
    cudaGetSymbolAddress((void**)&pq,    g_q);
    cudaGetSymbolAddress((void**)&pkv,   g_kv);
    cudaGetSymbolAddress((void**)&pqp,   g_qp);
    cudaGetSymbolAddress((void**)&pkvp,  g_kvp);
    cudaGetSymbolAddress((void**)&pocat, g_ocat);

    cudaFuncSetAttribute(k_scores, cudaFuncAttributeMaxDynamicSharedMemorySize, SC_SMEM);
    cudaFuncSetAttribute(k_opair,  cudaFuncAttributeMaxDynamicSharedMemorySize, OP_SMEM);

    // projections (one launch)
    gemm_proj<<<dim3(19, 12), 256>>>(s, w_q, b_q, pq, w_kv, b_kv, pkv,
                                     w_qp, b_qp, pqp, w_kvp, b_kvp, pkvp);
    // point transform
    k_points<<<NRES, 192>>>(rot, trans);
    // E = s1*qk - |wpt|*ptdist + mask  -> g_a
    k_qkpt<<<dim3(12, 12, 12), 256>>>(mask, hwts);
    // fused: E + bmat, softmax -> g_a (z pass 1)
    k_scores<<<NRES, 256, SC_SMEM>>>(z, w_b, b_b);
    // attention outputs
    k_av<<<dim3(12, 12), 256>>>();
    k_opair<<<NRES, 256, OP_SMEM>>>(z);   // z pass 2
    k_finish<<<NRES, 192>>>(rot, trans);
    // output projection
    gemm_abt<<<dim3(6, 12), 256>>>(pocat, w_out, b_out, out, 384, 2112);
}